// round 9
// baseline (speedup 1.0000x reference)
#include <cuda_runtime.h>
#include <cuda_bf16.h>
#include <cstdint>
#include <math.h>

#define BB 64
#define TT 256
#define HH 256
#define DD 128

// ---- scratch (device globals: no allocation allowed) ----
__device__ float g_xproj[(size_t)BB * TT * 768];   // [b*T+t][768]
__device__ float g_enc[(size_t)BB * TT * HH];      // [b*T+t][256]

// output layout (floats), concatenated in reference return order:
// mean_z [64,256,8] | chol_z [8,64,256,256] | mean_x [16384,8] | cov_x [16384,8,8]
#define OFF_MZ   0ull
#define OFF_CHOL 131072ull
#define OFF_MX   33685504ull
#define OFF_CX   33816576ull
#define CHOL_F4  8388608   // 33554432 floats / 4

// GRU dynamic smem layout (floats):
//   [0, 1024)     h_s   [phase][batch][HH]
//   [1024, 4160)  red   64 rows * 49 stride
//   [4160, 20800) Wn    64 rows * 260 stride (gate-n weight pairs, k-consecutive)
#define GRU_HS_OFF   0
#define GRU_RED_OFF  1024
#define GRU_WN_OFF   4160
#define GRU_WN_STR   260
#define GRU_SMEM_BYTES  ((GRU_WN_OFF + 64 * GRU_WN_STR) * 4)   // 83200

// ---- packed f32x2 helpers ----
__device__ __forceinline__ uint64_t pack2(float lo, float hi) {
    uint64_t r;
    asm("mov.b64 %0, {%1, %2};" : "=l"(r) : "r"(__float_as_uint(lo)), "r"(__float_as_uint(hi)));
    return r;
}
__device__ __forceinline__ void unpack2(uint64_t v, float& lo, float& hi) {
    uint32_t a, b;
    asm("mov.b64 {%0, %1}, %2;" : "=r"(a), "=r"(b) : "l"(v));
    lo = __uint_as_float(a); hi = __uint_as_float(b);
}
#define FMA2(acc, a, b) \
    asm("fma.rn.f32x2 %0, %1, %2, %3;" : "=l"(acc) : "l"(a), "l"(b), "l"(acc))
#define LDS2U64(r0, r1, addr) \
    asm("ld.shared.v2.u64 {%0, %1}, [%2];" : "=l"(r0), "=l"(r1) : "r"(addr))

// ============================================================
// 1) x_proj = y @ W_ih^T + b_ih : [16384,128] x [128,768]
//    + fused chol_z zero-fill (HBM stores hidden behind FMA work)
// ============================================================
__global__ void __launch_bounds__(256) xproj_kernel(const float* __restrict__ y,
                                                    const float* __restrict__ Wih,
                                                    const float* __restrict__ bih,
                                                    float4* __restrict__ chol4)
{
    __shared__ float As[64][68];   // [k][m]
    __shared__ float Bs[64][68];   // [k][n]
    const int tid = threadIdx.x;
    const int tx = tid & 15;       // n/4
    const int ty = tid >> 4;       // m/4
    const int m0 = blockIdx.x * 64;
    const int n0 = blockIdx.y * 64;

    // fused zero-fill of the chol region: 3072 CTAs x 2731 float4
    {
        const int bid = blockIdx.y * gridDim.x + blockIdx.x;   // 0..3071
        const size_t start = (size_t)bid * 2731;
        const float4 z = make_float4(0.f, 0.f, 0.f, 0.f);
        for (int k = tid; k < 2731; k += 256) {
            size_t idx = start + k;
            if (idx < CHOL_F4) chol4[idx] = z;
        }
    }

    float acc[4][4];
#pragma unroll
    for (int i = 0; i < 4; i++)
#pragma unroll
        for (int j = 0; j < 4; j++) acc[i][j] = 0.f;

    for (int kp = 0; kp < 128; kp += 64) {
        __syncthreads();
#pragma unroll
        for (int l = 0; l < 4; l++) {
            int lin = tid + l * 256;
            int row = lin >> 4;
            int kq  = lin & 15;
            float4 va = *(const float4*)(y   + (size_t)(m0 + row) * DD + kp + kq * 4);
            float4 vb = *(const float4*)(Wih + (size_t)(n0 + row) * DD + kp + kq * 4);
            As[kq * 4 + 0][row] = va.x; As[kq * 4 + 1][row] = va.y;
            As[kq * 4 + 2][row] = va.z; As[kq * 4 + 3][row] = va.w;
            Bs[kq * 4 + 0][row] = vb.x; Bs[kq * 4 + 1][row] = vb.y;
            Bs[kq * 4 + 2][row] = vb.z; Bs[kq * 4 + 3][row] = vb.w;
        }
        __syncthreads();
#pragma unroll
        for (int k = 0; k < 64; k++) {
            float4 av = *(const float4*)&As[k][ty * 4];
            float4 bv = *(const float4*)&Bs[k][tx * 4];
            float a[4] = {av.x, av.y, av.z, av.w};
            float b[4] = {bv.x, bv.y, bv.z, bv.w};
#pragma unroll
            for (int i = 0; i < 4; i++)
#pragma unroll
                for (int j = 0; j < 4; j++) acc[i][j] = fmaf(a[i], b[j], acc[i][j]);
        }
    }
#pragma unroll
    for (int j = 0; j < 4; j++) {
        float b = bih[n0 + tx * 4 + j];
#pragma unroll
        for (int i = 0; i < 4; i++) acc[i][j] += b;
    }
#pragma unroll
    for (int i = 0; i < 4; i++) {
        float* o = g_xproj + (size_t)(m0 + ty * 4 + i) * 768 + n0 + tx * 4;
        *(float4*)o = make_float4(acc[i][0], acc[i][1], acc[i][2], acc[i][3]);
    }
}

// ============================================================
// 2) GRU: 32 clusters x 4 CTAs, 2 batches/cluster.
//    CTA rank m owns hidden units [m*64, m*64+64) for all 3 gates.
//    Gates r,z weights in REGISTERS as k-pairs (FFMA2); gate-n
//    weights in dynamic SMEM. h double-buffered in SMEM, broadcast
//    via st.shared::cluster + barrier.cluster.
// ============================================================
__global__ void __cluster_dims__(4, 1, 1) __launch_bounds__(512, 1)
gru_kernel(const float* __restrict__ Whh, const float* __restrict__ bhh)
{
    extern __shared__ float dsm[];
    float* h_s = dsm + GRU_HS_OFF;     // [(ph*2 + b)*HH + idx]
    float* red = dsm + GRU_RED_OFF;    // [j*49 + slot]
    float* Wn  = dsm + GRU_WN_OFF;     // [j*GRU_WN_STR + k]

    const int tid  = threadIdx.x;
    const int j    = tid & 63;
    const int ks   = tid >> 6;                 // 0..7 (k-slice of 32)
    const int rank = blockIdx.x & 3;
    const int u0   = rank * 64;
    const int bg   = (blockIdx.x >> 2) * 2;    // global batch base

    // register-resident W for gates r,z as k-pairs
    uint64_t Wp[2][16];
#pragma unroll
    for (int g = 0; g < 2; g++) {
        const float4* wp = (const float4*)(Whh + (size_t)(g * HH + u0 + j) * HH + ks * 32);
#pragma unroll
        for (int q = 0; q < 8; q++) {
            float4 v = wp[q];
            Wp[g][2 * q + 0] = pack2(v.x, v.y);
            Wp[g][2 * q + 1] = pack2(v.z, v.w);
        }
    }
    // SMEM-resident gate-n weights (k-consecutive in each row)
    {
        const float4* wp = (const float4*)(Whh + (size_t)(2 * HH + u0 + j) * HH + ks * 32);
        float4* dp = (float4*)&Wn[j * GRU_WN_STR + ks * 32];
#pragma unroll
        for (int q = 0; q < 8; q++) dp[q] = wp[q];
    }
    float bh0 = 0.f, bh1 = 0.f, bh2 = 0.f;
    if (tid < 128) {
        int jr = tid & 63;
        bh0 = bhh[u0 + jr];
        bh1 = bhh[HH + u0 + jr];
        bh2 = bhh[2 * HH + u0 + jr];
    }
    for (int i = tid; i < 2 * 2 * HH; i += 512) h_s[i] = 0.f;

    uint32_t hbase, wnbase;
    asm("{ .reg .u64 t; cvta.to.shared.u64 t, %1; cvt.u32.u64 %0, t; }"
        : "=r"(hbase) : "l"((void*)h_s));
    wnbase = hbase + (GRU_WN_OFF - GRU_HS_OFF) * 4;

    const uint32_t h0base = hbase + ks * 128;
    const uint32_t wna = wnbase + (uint32_t)(j * GRU_WN_STR + ks * 32) * 4;

    __syncthreads();
    asm volatile("barrier.cluster.arrive.aligned;" ::: "memory");
    asm volatile("barrier.cluster.wait.aligned;" ::: "memory");

    for (int t = 0; t < TT; t++) {
        const int ph = t & 1;
        float xr = 0.f, xz = 0.f, xn = 0.f;
        if (tid < 128) {
            const int b = tid >> 6, jr = tid & 63;
            const float* xp = g_xproj + ((size_t)(bg + b) * TT + t) * 768 + u0 + jr;
            xr = xp[0]; xz = xp[HH]; xn = xp[2 * HH];
        }
        // packed partial dots: 3 gates x 2 batches over 32 k's (16 pairs)
        uint64_t a00 = 0, a01 = 0, a10 = 0, a11 = 0, a20 = 0, a21 = 0;
        const uint32_t h0a = h0base + (uint32_t)(ph * 2 + 0) * (HH * 4);
        const uint32_t h1a = h0a + HH * 4;
#pragma unroll
        for (int p = 0; p < 8; p++) {
            uint64_t h0x, h0y, h1x, h1y, wx, wy;
            LDS2U64(h0x, h0y, h0a + p * 16);
            LDS2U64(h1x, h1y, h1a + p * 16);
            LDS2U64(wx,  wy,  wna + p * 16);
            FMA2(a00, Wp[0][2 * p], h0x); FMA2(a00, Wp[0][2 * p + 1], h0y);
            FMA2(a01, Wp[0][2 * p], h1x); FMA2(a01, Wp[0][2 * p + 1], h1y);
            FMA2(a10, Wp[1][2 * p], h0x); FMA2(a10, Wp[1][2 * p + 1], h0y);
            FMA2(a11, Wp[1][2 * p], h1x); FMA2(a11, Wp[1][2 * p + 1], h1y);
            FMA2(a20, wx, h0x); FMA2(a20, wy, h0y);
            FMA2(a21, wx, h1x); FMA2(a21, wy, h1y);
        }
        float lo, hi, s00, s01, s10, s11, s20, s21;
        unpack2(a00, lo, hi); s00 = lo + hi;
        unpack2(a01, lo, hi); s01 = lo + hi;
        unpack2(a10, lo, hi); s10 = lo + hi;
        unpack2(a11, lo, hi); s11 = lo + hi;
        unpack2(a20, lo, hi); s20 = lo + hi;
        unpack2(a21, lo, hi); s21 = lo + hi;

        float* rbase = red + j * 49;
        rbase[ks]      = s00; rbase[8 + ks]  = s01;
        rbase[16 + ks] = s10; rbase[24 + ks] = s11;
        rbase[32 + ks] = s20; rbase[40 + ks] = s21;
        __syncthreads();
        if (tid < 128) {
            const int b = tid >> 6, jr = tid & 63;
            const float* rp = red + jr * 49 + b * 8;
            float sr = bh0, sz = bh1, sn = bh2;
#pragma unroll
            for (int k = 0; k < 8; k++) {
                sr += rp[k]; sz += rp[16 + k]; sn += rp[32 + k];
            }
            float r = 1.f / (1.f + expf(-(xr + sr)));
            float z = 1.f / (1.f + expf(-(xz + sz)));
            float n = tanhf(xn + r * sn);
            float hold = h_s[(ph * 2 + b) * HH + u0 + jr];
            float hnew = fmaf(z, hold - n, n);   // (1-z)*n + z*h
            g_enc[((size_t)(bg + b) * TT + t) * HH + u0 + jr] = hnew;
            uint32_t laddr = hbase + (uint32_t)(((((ph ^ 1) * 2 + b) * HH) + u0 + jr) * 4);
#pragma unroll
            for (int p = 0; p < 4; p++) {
                uint32_t raddr;
                asm("mapa.shared::cluster.u32 %0, %1, %2;" : "=r"(raddr) : "r"(laddr), "r"(p));
                asm volatile("st.shared::cluster.f32 [%0], %1;" :: "r"(raddr), "f"(hnew));
            }
        }
        asm volatile("barrier.cluster.arrive.aligned;" ::: "memory");
        asm volatile("barrier.cluster.wait.aligned;" ::: "memory");
    }
}

// ============================================================
// 3) heads: enc[16384,256] x W_all^T[256,96] + transforms + scatter
//    r: [0,8)=mean_z [8,16)=mean_x [16,32)=bd_z [32,96)=cov_x
//    Anchor (mean_x[b,0,:2]) computed in a pre-pass per block
//    (each block's 128 rows live in one batch: b = blockIdx.x>>1).
// ============================================================
__global__ void __launch_bounds__(384) heads_kernel(
    const float* __restrict__ Wmz, const float* __restrict__ bmz,
    const float* __restrict__ Wmx, const float* __restrict__ bmx,
    const float* __restrict__ Wpz, const float* __restrict__ bpz,
    const float* __restrict__ Wcx, const float* __restrict__ bcx,
    float* __restrict__ out)
{
    __shared__ float encsm[256];
    __shared__ float red[384];
    __shared__ float anchor_sm[2];

    const int tid = threadIdx.x;
    const int r  = tid % 96;
    const int kc = tid / 96;

    // select weight row + bias for this r
    const float* wrow;
    float bias;
    if (r < 8)       { wrow = Wmz + (size_t)r * HH;        bias = bmz[r]; }
    else if (r < 16) { wrow = Wmx + (size_t)(r - 8) * HH;  bias = bmx[r - 8]; }
    else if (r < 32) { wrow = Wpz + (size_t)(r - 16) * HH; bias = bpz[r - 16]; }
    else             { wrow = Wcx + (size_t)(r - 32) * HH; bias = bcx[r - 32]; }

    float W[64];
    {
        const float4* wp = (const float4*)(wrow + kc * 64);
#pragma unroll
        for (int q = 0; q < 16; q++) {
            float4 v = wp[q];
            W[4 * q + 0] = v.x; W[4 * q + 1] = v.y;
            W[4 * q + 2] = v.z; W[4 * q + 3] = v.w;
        }
    }

    const int row0 = blockIdx.x * 128;
    const int bbase = (blockIdx.x >> 1) << 8;   // first row (t=0) of this block's batch

    // anchor pre-pass: mean_x[b, 0, 0:2] (incl. bias)
    {
        if (tid < 64)
            *(float4*)&encsm[tid * 4] = *(const float4*)(g_enc + (size_t)bbase * HH + tid * 4);
        __syncthreads();
        float s = 0.f;
        const float4* ev = (const float4*)&encsm[kc * 64];
#pragma unroll
        for (int q = 0; q < 16; q++) {
            float4 v = ev[q];
            s = fmaf(W[4 * q + 0], v.x, s);
            s = fmaf(W[4 * q + 1], v.y, s);
            s = fmaf(W[4 * q + 2], v.z, s);
            s = fmaf(W[4 * q + 3], v.w, s);
        }
        red[kc * 96 + r] = s;
        __syncthreads();
        if (tid == 8 || tid == 9) {
            anchor_sm[tid - 8] =
                red[tid] + red[96 + tid] + red[192 + tid] + red[288 + tid] + bias;
        }
    }

    for (int i = 0; i < 128; i++) {
        const int row = row0 + i;
        __syncthreads();
        if (tid < 64) {
            *(float4*)&encsm[tid * 4] = *(const float4*)(g_enc + (size_t)row * HH + tid * 4);
        }
        __syncthreads();
        float s = 0.f;
        const float4* ev = (const float4*)&encsm[kc * 64];
#pragma unroll
        for (int q = 0; q < 16; q++) {
            float4 v = ev[q];
            s = fmaf(W[4 * q + 0], v.x, s);
            s = fmaf(W[4 * q + 1], v.y, s);
            s = fmaf(W[4 * q + 2], v.z, s);
            s = fmaf(W[4 * q + 3], v.w, s);
        }
        red[kc * 96 + r] = s;
        __syncthreads();
        if (tid < 96) {
            float v = red[tid] + red[96 + tid] + red[192 + tid] + red[288 + tid] + bias;
            const int b = row >> 8, t = row & 255;
            if (tid < 8) {
                out[OFF_MZ + (size_t)row * 8 + tid] = v;
            } else if (tid < 16) {
                int d = tid - 8;
                float a = (d < 2) ? anchor_sm[d] : 0.f;
                out[OFF_MX + (size_t)row * 8 + d] = v - a;
            } else if (tid < 32) {
                int d = tid - 16;
                if (d < 8) {
                    // diag: softplus
                    float sp = (v > 20.f) ? v : log1pf(expf(v));
                    out[OFF_CHOL + (((size_t)d * BB + b) * TT + t) * TT + t] = sp;
                } else {
                    int dz = d - 8;
                    if (t < TT - 1)
                        out[OFF_CHOL + (((size_t)dz * BB + b) * TT + t) * TT + (t + 1)] = v;
                }
            } else {
                out[OFF_CX + (size_t)row * 64 + (tid - 32)] = v;
            }
        }
    }
}

extern "C" void kernel_launch(void* const* d_in, const int* in_sizes, int n_in,
                              void* d_out, int out_size)
{
    const float* y    = (const float*)d_in[0];
    const float* Wih  = (const float*)d_in[1];
    const float* Whh  = (const float*)d_in[2];
    const float* bih  = (const float*)d_in[3];
    const float* bhh  = (const float*)d_in[4];
    const float* Wmz  = (const float*)d_in[5];
    const float* bmz  = (const float*)d_in[6];
    const float* Wmx  = (const float*)d_in[7];
    const float* bmx  = (const float*)d_in[8];
    const float* Wpz  = (const float*)d_in[9];
    const float* bpz  = (const float*)d_in[10];
    const float* Wcx  = (const float*)d_in[11];
    const float* bcx  = (const float*)d_in[12];
    float* out = (float*)d_out;

    cudaFuncSetAttribute(gru_kernel, cudaFuncAttributeMaxDynamicSharedMemorySize,
                         GRU_SMEM_BYTES);

    dim3 gx(256, 12);
    xproj_kernel<<<gx, 256>>>(y, Wih, bih, (float4*)(out + OFF_CHOL));

    gru_kernel<<<128, 512, GRU_SMEM_BYTES>>>(Whh, bhh);

    heads_kernel<<<128, 384>>>(Wmz, bmz, Wmx, bmx, Wpz, bpz, Wcx, bcx, out);
}